// round 5
// baseline (speedup 1.0000x reference)
#include <cuda_runtime.h>
#include <cuda_bf16.h>
#include <cstdint>
#include <math.h>

// Sqrtm Newton-Schulz on tensor cores via mma.sync bf16 (sm_80+ PTX; harness
// PTX target is plain sm_103, which rejects tcgen05).
// Chain (verified, rel_err 1.3e-11 vs reference):
//   normA = sum(x); A = x/normA; Z0 = 1.5I - 0.5A
//   Y1 = A@Z0
//   3x: ZY = 0.5*Y - 0.5*(Z@Y); Y' = Y@ZY; Z' = ZY@Z
//   T = 0.5*Y - 0.5*(Y@Z); out = (T@Y)*sqrt(normA)
// All chain matrices are symmetric => row-major B == col-major B operand.
// fp32 stored as bf16 hi+lo; product via 3 MMAs: Ah@Bh + Ah@Bl + Al@Bh.
//
// R5: 8 warps, 64x32 warp tile, register-level frag double-buffering,
// 3-stage (BK=64) cp.async pipeline, one sync per chunk.

#define DMAT 256
#define MSZ  65536
#define BATCH 256

#define STAGE 65536              // Ah 16K | Al 16K | Bh 16K | Bl 16K
#define NSTAGE 3
#define SMEM_TOTAL (NSTAGE * STAGE)

__device__ __nv_bfloat16 g_hi[5][(size_t)BATCH * MSZ];
__device__ __nv_bfloat16 g_lo[5][(size_t)BATCH * MSZ];
__device__ float g_inv[BATCH];
__device__ float g_sqrt[BATCH];

__device__ __forceinline__ uint32_t smem_u32(const void* p) {
    uint32_t a;
    asm("{ .reg .u64 t; cvta.to.shared.u64 t, %1; cvt.u32.u64 %0, t; }" : "=r"(a) : "l"(p));
    return a;
}

#define LDSM4(r, a) \
    asm volatile("ldmatrix.sync.aligned.m8n8.x4.shared.b16 {%0,%1,%2,%3}, [%4];" \
        : "=r"((r)[0]), "=r"((r)[1]), "=r"((r)[2]), "=r"((r)[3]) : "r"(a))

#define MMA(d, a, bb) \
    asm volatile("mma.sync.aligned.m16n8k16.row.col.f32.bf16.bf16.f32 " \
        "{%0,%1,%2,%3}, {%4,%5,%6,%7}, {%8,%9}, {%0,%1,%2,%3};" \
        : "+f"((d)[0]), "+f"((d)[1]), "+f"((d)[2]), "+f"((d)[3]) \
        : "r"((a)[0]), "r"((a)[1]), "r"((a)[2]), "r"((a)[3]), \
          "r"((bb)[0]), "r"((bb)[1]))

// ---------------------------------------------------------------------------
__global__ void norm_kernel(const float* __restrict__ x) {
    const int b = blockIdx.x;
    const float* p = x + (size_t)b * MSZ;
    float s = 0.f;
    for (int i = threadIdx.x; i < MSZ; i += 256) s += p[i];
    __shared__ float sh[256];
    sh[threadIdx.x] = s;
    __syncthreads();
    for (int off = 128; off > 0; off >>= 1) {
        if (threadIdx.x < off) sh[threadIdx.x] += sh[threadIdx.x + off];
        __syncthreads();
    }
    if (threadIdx.x == 0) {
        float n = sh[0];
        g_inv[b] = 1.0f / n;
        g_sqrt[b] = sqrtf(n);
    }
}

// A = x*inv -> buf0;  Z0 = 1.5I - 0.5A -> buf3  (bf16 hi/lo pairs)
__global__ void setup_kernel(const float* __restrict__ x) {
    const size_t idx = (size_t)blockIdx.x * blockDim.x + threadIdx.x;
    const int b = (int)(idx >> 16);
    const int ij = (int)(idx & (MSZ - 1));
    const float a = x[idx] * g_inv[b];
    const int i = ij >> 8, j = ij & 255;
    const float z = (i == j ? 1.5f : 0.0f) - 0.5f * a;

    __nv_bfloat16 ah = __float2bfloat16_rn(a);
    __nv_bfloat16 al = __float2bfloat16_rn(a - __bfloat162float(ah));
    __nv_bfloat16 zh = __float2bfloat16_rn(z);
    __nv_bfloat16 zl = __float2bfloat16_rn(z - __bfloat162float(zh));
    g_hi[0][idx] = ah;  g_lo[0][idx] = al;
    g_hi[3][idx] = zh;  g_lo[3][idx] = zl;
}

// ---------------------------------------------------------------------------
// Batched GEMM step: CTA = 128x128 tile, 256 threads, 8 warps (2M x 4N),
// warp tile 64x32.
// mode 0: C = A@B               -> hi/lo pair in buf idst
// mode 1: C = 0.5*Y - 0.5*(A@B) -> pair in buf idst   (Y = buf iy)
// mode 2: C = (A@B)*sqrt(normA) -> fp32 to outp
__global__ void __launch_bounds__(256, 1)
gemm_mma(int ia, int ib, int iy, int idst, int mode, float* __restrict__ outp)
{
    extern __shared__ __align__(128) char smem[];
    const uint32_t sbase = smem_u32(smem);
    const int tid = threadIdx.x, wid = tid >> 5, lane = tid & 31;
    const int b = blockIdx.z;
    const int mBase = blockIdx.y * 128, nBase = blockIdx.x * 128;
    const size_t mo = (size_t)b * MSZ;

    const __nv_bfloat16* Ah = g_hi[ia] + mo;
    const __nv_bfloat16* Al = g_lo[ia] + mo;
    const __nv_bfloat16* Bh = g_hi[ib] + mo;
    const __nv_bfloat16* Bl = g_lo[ib] + mo;

    const int warpM = wid & 1;   // 2 warps over M (64 rows each)
    const int warpN = wid >> 1;  // 4 warps over N (32 cols each)

    float acc[4][4][4] = {};     // [mt][nt][frag]

    // ---- global -> smem (cp.async), one K-chunk of 64 cols, 4 planes ----
    auto load_chunk = [&](int stage, int c) {
        const uint32_t sb = sbase + stage * STAGE;
        const int kc = c * 64;
        #pragma unroll
        for (int it = 0; it < 16; ++it) {
            const int i = tid + it * 256;
            const int plane = i >> 10;           // 0:Ah 1:Al 2:Bh 3:Bl
            const int rem = i & 1023;
            const int row = rem >> 3, seg = rem & 7;
            const __nv_bfloat16* sp =
                (plane == 0) ? Ah : (plane == 1) ? Al : (plane == 2) ? Bh : Bl;
            const int gRow = ((plane < 2) ? mBase : nBase) + row;
            const void* src = sp + (size_t)gRow * DMAT + kc + seg * 8;
            const uint32_t dst = sb + plane * 16384 + row * 128 +
                                 ((seg ^ (row & 7)) * 16);
            asm volatile("cp.async.cg.shared.global [%0], [%1], 16;"
                         :: "r"(dst), "l"(src));
        }
        asm volatile("cp.async.commit_group;" ::: "memory");
    };

    // ---- fragment buffers (double-buffered across ks steps) ----
    uint32_t fah[2][4][4], fal[2][4][4], fbh[2][4][2], fbl[2][4][2];

    const int r16 = lane & 15, chf = lane >> 4, xr = lane & 7;
    const uint32_t aRow0 = (uint32_t)(warpM * 64 + r16) * 128;
    const uint32_t bRow0 = 32768u + (uint32_t)(warpN * 32 + r16) * 128;

    auto load_frags = [&](int fb, uint32_t sb, int ks) {
        const uint32_t sw = (uint32_t)(((ks * 2 + chf) ^ xr) * 16);
        #pragma unroll
        for (int mt = 0; mt < 4; ++mt) {
            const uint32_t addr = sb + aRow0 + (uint32_t)(mt * 2048) + sw;
            LDSM4(fah[fb][mt], addr);
            LDSM4(fal[fb][mt], addr + 16384);
        }
        #pragma unroll
        for (int np = 0; np < 2; ++np) {
            const uint32_t addr = sb + bRow0 + (uint32_t)(np * 2048) + sw;
            uint32_t t[4];
            LDSM4(t, addr);
            fbh[fb][np * 2][0] = t[0];      fbh[fb][np * 2][1] = t[2];
            fbh[fb][np * 2 + 1][0] = t[1];  fbh[fb][np * 2 + 1][1] = t[3];
            LDSM4(t, addr + 16384);
            fbl[fb][np * 2][0] = t[0];      fbl[fb][np * 2][1] = t[2];
            fbl[fb][np * 2 + 1][0] = t[1];  fbl[fb][np * 2 + 1][1] = t[3];
        }
    };

    auto mma_all = [&](int fb) {
        #pragma unroll
        for (int mt = 0; mt < 4; ++mt)
            #pragma unroll
            for (int nt = 0; nt < 4; ++nt)
                MMA(acc[mt][nt], fah[fb][mt], fbh[fb][nt]);
        #pragma unroll
        for (int mt = 0; mt < 4; ++mt)
            #pragma unroll
            for (int nt = 0; nt < 4; ++nt)
                MMA(acc[mt][nt], fah[fb][mt], fbl[fb][nt]);
        #pragma unroll
        for (int mt = 0; mt < 4; ++mt)
            #pragma unroll
            for (int nt = 0; nt < 4; ++nt)
                MMA(acc[mt][nt], fal[fb][mt], fbh[fb][nt]);
    };

    // ---- prologue: commit chunks 0,1,2 into stages 0,1,2 ----
    load_chunk(0, 0);
    load_chunk(1, 1);
    load_chunk(2, 2);

    asm volatile("cp.async.wait_group 1;" ::: "memory");  // chunks 0,1 done
    __syncthreads();
    load_frags(0, sbase, 0);

    #pragma unroll
    for (int c = 0; c < 4; ++c) {
        const uint32_t sb = sbase + (uint32_t)((c % 3) * STAGE);
        const uint32_t sbn = sbase + (uint32_t)(((c + 1) % 3) * STAGE);
        #pragma unroll
        for (int ks = 0; ks < 4; ++ks) {
            if (ks < 3)           load_frags((ks + 1) & 1, sb, ks + 1);
            else if (c < 3)       load_frags(0, sbn, 0);
            mma_all(ks & 1);
        }
        if (c == 0) {
            __syncthreads();                 // all warps done reading stage 0
            load_chunk(0, 3);                // chunk 3 -> stage 0
            asm volatile("cp.async.wait_group 1;" ::: "memory");  // chunk 2
            __syncthreads();
        } else if (c == 1) {
            asm volatile("cp.async.wait_group 0;" ::: "memory");  // chunk 3
            __syncthreads();
        }
    }

    // ---- epilogue ----
    const float sc = g_sqrt[b];
    const int r4 = lane >> 2, c2 = (lane & 3) * 2;
    const __nv_bfloat16* Yh = g_hi[iy] + mo;
    const __nv_bfloat16* Yl = g_lo[iy] + mo;
    __nv_bfloat16* Dh = g_hi[idst] + mo;
    __nv_bfloat16* Dl = g_lo[idst] + mo;
    float* Of = outp + mo;

    #pragma unroll
    for (int mt = 0; mt < 4; ++mt)
        #pragma unroll
        for (int nt = 0; nt < 4; ++nt)
            #pragma unroll
            for (int h = 0; h < 2; ++h) {
                const int row = mBase + warpM * 64 + mt * 16 + r4 + h * 8;
                const int col = nBase + warpN * 32 + nt * 8 + c2;
                float v0 = acc[mt][nt][h * 2];
                float v1 = acc[mt][nt][h * 2 + 1];
                const size_t off = (size_t)row * DMAT + col;
                if (mode == 1) {
                    const uint32_t hw = *(const uint32_t*)(Yh + off);
                    const uint32_t lw = *(const uint32_t*)(Yl + off);
                    const float y0 = __uint_as_float(hw << 16) +
                                     __uint_as_float(lw << 16);
                    const float y1 = __uint_as_float(hw & 0xffff0000u) +
                                     __uint_as_float(lw & 0xffff0000u);
                    v0 = 0.5f * y0 - 0.5f * v0;
                    v1 = 0.5f * y1 - 0.5f * v1;
                }
                if (mode == 2) {
                    *(float2*)(Of + off) = make_float2(v0 * sc, v1 * sc);
                } else {
                    const __nv_bfloat16 h0 = __float2bfloat16_rn(v0);
                    const __nv_bfloat16 h1 = __float2bfloat16_rn(v1);
                    const __nv_bfloat16 l0 =
                        __float2bfloat16_rn(v0 - __bfloat162float(h0));
                    const __nv_bfloat16 l1 =
                        __float2bfloat16_rn(v1 - __bfloat162float(h1));
                    __nv_bfloat162 hp = __halves2bfloat162(h0, h1);
                    __nv_bfloat162 lp = __halves2bfloat162(l0, l1);
                    *(uint32_t*)(Dh + off) = *(uint32_t*)&hp;
                    *(uint32_t*)(Dl + off) = *(uint32_t*)&lp;
                }
            }
}

// ---------------------------------------------------------------------------
extern "C" void kernel_launch(void* const* d_in, const int* in_sizes, int n_in,
                              void* d_out, int out_size) {
    const float* x = (const float*)d_in[0];
    float* out = (float*)d_out;
    (void)in_sizes; (void)n_in; (void)out_size;

    cudaFuncSetAttribute(gemm_mma, cudaFuncAttributeMaxDynamicSharedMemorySize,
                         SMEM_TOTAL);

    norm_kernel<<<BATCH, 256>>>(x);
    setup_kernel<<<(BATCH * MSZ) / 256, 256>>>(x);

    dim3 grid(2, 2, BATCH);
    #define GEMM(ia, ib, iy, idst, mode) \
        gemm_mma<<<grid, 256, SMEM_TOTAL>>>(ia, ib, iy, idst, mode, out)

    GEMM(0, 3, 0, 1, 0);   // Y1(1) = A(0)@Z0(3)
    // iter 1
    GEMM(3, 1, 1, 2, 1);   // ZY(2) = 0.5*Y(1) - 0.5*Z(3)@Y(1)
    GEMM(1, 2, 0, 0, 0);   // Y2(0) = Y(1)@ZY(2)
    GEMM(2, 3, 0, 4, 0);   // Z2(4) = ZY(2)@Z(3)
    // iter 2
    GEMM(4, 0, 0, 2, 1);   // ZY(2) = 0.5*Y(0) - 0.5*Z(4)@Y(0)
    GEMM(0, 2, 0, 1, 0);   // Y3(1) = Y(0)@ZY(2)
    GEMM(2, 4, 0, 3, 0);   // Z3(3) = ZY(2)@Z(4)
    // iter 3
    GEMM(3, 1, 1, 2, 1);   // ZY(2) = 0.5*Y(1) - 0.5*Z(3)@Y(1)
    GEMM(1, 2, 0, 0, 0);   // Y4(0) = Y(1)@ZY(2)
    GEMM(2, 3, 0, 4, 0);   // Z4(4) = ZY(2)@Z(3)
    // final
    GEMM(0, 4, 0, 2, 1);   // T(2) = 0.5*Y(0) - 0.5*Y(0)@Z(4)
    GEMM(2, 0, 0, 0, 2);   // out = T(2)@Y(0) * sqrt(normA)
    #undef GEMM
}

// round 6
// speedup vs baseline: 1.2136x; 1.2136x over previous
#include <cuda_runtime.h>
#include <cuda_bf16.h>
#include <cstdint>
#include <math.h>

// Sqrtm Newton-Schulz on tensor cores via mma.sync bf16 (sm_80+ PTX; harness
// PTX target is plain sm_103 which rejects tcgen05).
// Chain (verified):
//   normA = sum(x); A = x/normA; Z0 = 1.5I - 0.5A
//   Y1 = A@Z0
//   3x: ZY = 0.5*Y - 0.5*(Z@Y); Y' = Y@ZY; Z' = ZY@Z
//   T = 0.5*Y - 0.5*(Y@Z); out = (T@Y)*sqrt(normA)
// All chain matrices are symmetric polynomials in A => every GEMM output is
// symmetric. R6: compute only 3 of 4 128x128 tiles per matrix; tile (1,0) is
// written by tile (0,1)'s epilogue as a smem-staged transpose. Plane-major
// MMA ordering for longer dependency distance. R4 execution shape (512 thr).

#define DMAT 256
#define MSZ  65536
#define BATCH 256

#define STAGE 65536              // Ah 16K | Al 16K | Bh 16K | Bl 16K
#define SMEM_TOTAL (2 * STAGE)

__device__ __nv_bfloat16 g_hi[5][(size_t)BATCH * MSZ];
__device__ __nv_bfloat16 g_lo[5][(size_t)BATCH * MSZ];
__device__ float g_inv[BATCH];
__device__ float g_sqrt[BATCH];

__device__ __forceinline__ uint32_t smem_u32(const void* p) {
    uint32_t a;
    asm("{ .reg .u64 t; cvta.to.shared.u64 t, %1; cvt.u32.u64 %0, t; }" : "=r"(a) : "l"(p));
    return a;
}

#define LDSM4(r, a) \
    asm volatile("ldmatrix.sync.aligned.m8n8.x4.shared.b16 {%0,%1,%2,%3}, [%4];" \
        : "=r"((r)[0]), "=r"((r)[1]), "=r"((r)[2]), "=r"((r)[3]) : "r"(a))

#define MMA(d, a, bb) \
    asm volatile("mma.sync.aligned.m16n8k16.row.col.f32.bf16.bf16.f32 " \
        "{%0,%1,%2,%3}, {%4,%5,%6,%7}, {%8,%9}, {%0,%1,%2,%3};" \
        : "+f"((d)[0]), "+f"((d)[1]), "+f"((d)[2]), "+f"((d)[3]) \
        : "r"((a)[0]), "r"((a)[1]), "r"((a)[2]), "r"((a)[3]), \
          "r"((bb)[0]), "r"((bb)[1]))

// ---------------------------------------------------------------------------
__global__ void norm_kernel(const float* __restrict__ x) {
    const int b = blockIdx.x;
    const float* p = x + (size_t)b * MSZ;
    float s = 0.f;
    for (int i = threadIdx.x; i < MSZ; i += 256) s += p[i];
    __shared__ float sh[256];
    sh[threadIdx.x] = s;
    __syncthreads();
    for (int off = 128; off > 0; off >>= 1) {
        if (threadIdx.x < off) sh[threadIdx.x] += sh[threadIdx.x + off];
        __syncthreads();
    }
    if (threadIdx.x == 0) {
        float n = sh[0];
        g_inv[b] = 1.0f / n;
        g_sqrt[b] = sqrtf(n);
    }
}

// A = x*inv -> buf0;  Z0 = 1.5I - 0.5A -> buf3  (bf16 hi/lo pairs)
__global__ void setup_kernel(const float* __restrict__ x) {
    const size_t idx = (size_t)blockIdx.x * blockDim.x + threadIdx.x;
    const int b = (int)(idx >> 16);
    const int ij = (int)(idx & (MSZ - 1));
    const float a = x[idx] * g_inv[b];
    const int i = ij >> 8, j = ij & 255;
    const float z = (i == j ? 1.5f : 0.0f) - 0.5f * a;

    __nv_bfloat16 ah = __float2bfloat16_rn(a);
    __nv_bfloat16 al = __float2bfloat16_rn(a - __bfloat162float(ah));
    __nv_bfloat16 zh = __float2bfloat16_rn(z);
    __nv_bfloat16 zl = __float2bfloat16_rn(z - __bfloat162float(zh));
    g_hi[0][idx] = ah;  g_lo[0][idx] = al;
    g_hi[3][idx] = zh;  g_lo[3][idx] = zl;
}

// ---------------------------------------------------------------------------
// Batched GEMM step. grid = (3 tiles, BATCH). 512 threads, 16 warps (4Mx4N),
// warp tile 32x32. tile 0 = block(0,0); tile 1 = block(0,1) + mirrored
// transpose to block(1,0); tile 2 = block(1,1).
// mode 0: C = A@B               -> hi/lo pair in buf idst
// mode 1: C = 0.5*Y - 0.5*(A@B) -> pair in buf idst   (Y = buf iy)
// mode 2: C = (A@B)*sqrt(normA) -> fp32 to outp
__global__ void __launch_bounds__(512, 1)
gemm_mma(int ia, int ib, int iy, int idst, int mode, float* __restrict__ outp)
{
    extern __shared__ __align__(128) char smem[];
    const uint32_t sbase = smem_u32(smem);
    const int tid = threadIdx.x, wid = tid >> 5, lane = tid & 31;
    const int tileId = blockIdx.x;
    const int b = blockIdx.y;
    const int mBase = (tileId == 2) ? 128 : 0;
    const int nBase = (tileId == 0) ? 0 : 128;
    const bool mir = (tileId == 1);
    const size_t mo = (size_t)b * MSZ;

    const __nv_bfloat16* Ah = g_hi[ia] + mo;
    const __nv_bfloat16* Al = g_lo[ia] + mo;
    const __nv_bfloat16* Bh = g_hi[ib] + mo;
    const __nv_bfloat16* Bl = g_lo[ib] + mo;

    const int warpM = wid & 3;   // 4 warps over M (32 rows each)
    const int warpN = wid >> 2;  // 4 warps over N (32 cols each)

    float acc[2][4][4] = {};     // [mt][nt][frag]

    // ---- global -> smem (cp.async), one K-chunk of 64 cols, 4 planes ----
    auto load_chunk = [&](int stage, int c) {
        const uint32_t sb = sbase + stage * STAGE;
        const int kc = c * 64;
        #pragma unroll
        for (int it = 0; it < 8; ++it) {
            const int i = tid + it * 512;
            const int plane = i >> 10;           // 0:Ah 1:Al 2:Bh 3:Bl
            const int rem = i & 1023;
            const int row = rem >> 3, seg = rem & 7;
            const __nv_bfloat16* sp =
                (plane == 0) ? Ah : (plane == 1) ? Al : (plane == 2) ? Bh : Bl;
            const int gRow = ((plane < 2) ? mBase : nBase) + row;
            const void* src = sp + (size_t)gRow * DMAT + kc + seg * 8;
            const uint32_t dst = sb + plane * 16384 + row * 128 +
                                 ((seg ^ (row & 7)) * 16);
            asm volatile("cp.async.cg.shared.global [%0], [%1], 16;"
                         :: "r"(dst), "l"(src));
        }
        asm volatile("cp.async.commit_group;" ::: "memory");
    };

    // ---- compute one K-chunk (4 x k16 steps), 3-product split ----
    const int r16 = lane & 15, chf = lane >> 4, xr = lane & 7;
    const uint32_t aRow0 = (uint32_t)(warpM * 32 + r16) * 128;
    const uint32_t bRow0 = 32768u + (uint32_t)(warpN * 32 + r16) * 128;

    auto compute_chunk = [&](int stage) {
        const uint32_t sb = sbase + stage * STAGE;
        #pragma unroll
        for (int ks = 0; ks < 4; ++ks) {
            const uint32_t sw = (uint32_t)(((ks * 2 + chf) ^ xr) * 16);
            uint32_t ahf[2][4], alf[2][4], bhf[4][2], blf[4][2];
            #pragma unroll
            for (int mt = 0; mt < 2; ++mt) {
                const uint32_t addr = sb + aRow0 + (uint32_t)(mt * 2048) + sw;
                LDSM4(ahf[mt], addr);            // plane Ah at +0
                LDSM4(alf[mt], addr + 16384);    // plane Al
            }
            #pragma unroll
            for (int np = 0; np < 2; ++np) {
                const uint32_t addr = sb + bRow0 + (uint32_t)(np * 2048) + sw;
                uint32_t t[4];
                LDSM4(t, addr);                  // plane Bh
                bhf[np * 2][0] = t[0];      bhf[np * 2][1] = t[2];
                bhf[np * 2 + 1][0] = t[1];  bhf[np * 2 + 1][1] = t[3];
                LDSM4(t, addr + 16384);          // plane Bl
                blf[np * 2][0] = t[0];      blf[np * 2][1] = t[2];
                blf[np * 2 + 1][0] = t[1];  blf[np * 2 + 1][1] = t[3];
            }
            // plane-major: max dependency distance per accumulator
            #pragma unroll
            for (int mt = 0; mt < 2; ++mt)
                #pragma unroll
                for (int nt = 0; nt < 4; ++nt)
                    MMA(acc[mt][nt], ahf[mt], bhf[nt]);
            #pragma unroll
            for (int mt = 0; mt < 2; ++mt)
                #pragma unroll
                for (int nt = 0; nt < 4; ++nt)
                    MMA(acc[mt][nt], ahf[mt], blf[nt]);
            #pragma unroll
            for (int mt = 0; mt < 2; ++mt)
                #pragma unroll
                for (int nt = 0; nt < 4; ++nt)
                    MMA(acc[mt][nt], alf[mt], bhf[nt]);
        }
    };

    load_chunk(0, 0);
    load_chunk(1, 1);
    #pragma unroll
    for (int c = 0; c < 4; ++c) {
        if (c < 3) asm volatile("cp.async.wait_group 1;" ::: "memory");
        else       asm volatile("cp.async.wait_group 0;" ::: "memory");
        __syncthreads();
        compute_chunk(c & 1);
        __syncthreads();
        if (c < 2) load_chunk(c & 1, c + 2);
    }

    // ---- epilogue ----
    const float sc = g_sqrt[b];
    const int r4 = lane >> 2, c2 = (lane & 3) * 2;
    const __nv_bfloat16* Yh = g_hi[iy] + mo;
    const __nv_bfloat16* Yl = g_lo[iy] + mo;
    __nv_bfloat16* Dh = g_hi[idst] + mo;
    __nv_bfloat16* Dl = g_lo[idst] + mo;
    float* Of = outp + mo;
    uint32_t* sm32 = (uint32_t*)smem;   // staging for mirror (pitch 129)

    #pragma unroll
    for (int mt = 0; mt < 2; ++mt)
        #pragma unroll
        for (int nt = 0; nt < 4; ++nt)
            #pragma unroll
            for (int h = 0; h < 2; ++h) {
                const int rloc = warpM * 32 + mt * 16 + r4 + h * 8;
                const int cloc = warpN * 32 + nt * 8 + c2;
                const int row = mBase + rloc, col = nBase + cloc;
                float v0 = acc[mt][nt][h * 2];
                float v1 = acc[mt][nt][h * 2 + 1];
                const size_t off = (size_t)row * DMAT + col;
                if (mode == 1) {
                    const uint32_t hw = *(const uint32_t*)(Yh + off);
                    const uint32_t lw = *(const uint32_t*)(Yl + off);
                    const float y0 = __uint_as_float(hw << 16) +
                                     __uint_as_float(lw << 16);
                    const float y1 = __uint_as_float(hw & 0xffff0000u) +
                                     __uint_as_float(lw & 0xffff0000u);
                    v0 = 0.5f * y0 - 0.5f * v0;
                    v1 = 0.5f * y1 - 0.5f * v1;
                }
                if (mode == 2) {
                    v0 *= sc;  v1 *= sc;
                    *(float2*)(Of + off) = make_float2(v0, v1);
                    if (mir) {
                        sm32[rloc * 129 + cloc]     = __float_as_uint(v0);
                        sm32[rloc * 129 + cloc + 1] = __float_as_uint(v1);
                    }
                } else {
                    const __nv_bfloat16 h0 = __float2bfloat16_rn(v0);
                    const __nv_bfloat16 h1 = __float2bfloat16_rn(v1);
                    const __nv_bfloat16 l0 =
                        __float2bfloat16_rn(v0 - __bfloat162float(h0));
                    const __nv_bfloat16 l1 =
                        __float2bfloat16_rn(v1 - __bfloat162float(h1));
                    __nv_bfloat162 hp = __halves2bfloat162(h0, h1);
                    __nv_bfloat162 lp = __halves2bfloat162(l0, l1);
                    const uint32_t hpw = *(uint32_t*)&hp;
                    const uint32_t lpw = *(uint32_t*)&lp;
                    *(uint32_t*)(Dh + off) = hpw;
                    *(uint32_t*)(Dl + off) = lpw;
                    if (mir) {
                        // pack (hi, lo) of each element into one word
                        sm32[rloc * 129 + cloc] =
                            (hpw & 0xffffu) | (lpw << 16);
                        sm32[rloc * 129 + cloc + 1] =
                            (hpw >> 16) | (lpw & 0xffff0000u);
                    }
                }
            }

    if (mir) {
        __syncthreads();
        // mirror block (1,0): rows 128..255, cols 0..127.
        // element (128+i, j) = comp(local row j, local col i) = sm32[j*129+i]
        #pragma unroll
        for (int it = 0; it < 16; ++it) {
            const int e = tid + it * 512;         // 0..8191 (pairs)
            const int i = e >> 6;                 // mirror row 0..127
            const int j = (e & 63) * 2;           // mirror col, even
            const uint32_t w0 = sm32[j * 129 + i];
            const uint32_t w1 = sm32[(j + 1) * 129 + i];
            const size_t off = (size_t)(128 + i) * DMAT + j;
            if (mode == 2) {
                *(float2*)(Of + off) =
                    make_float2(__uint_as_float(w0), __uint_as_float(w1));
            } else {
                *(uint32_t*)(Dh + off) = (w0 & 0xffffu) | (w1 << 16);
                *(uint32_t*)(Dl + off) = (w0 >> 16) | (w1 & 0xffff0000u);
            }
        }
    }
}

// ---------------------------------------------------------------------------
extern "C" void kernel_launch(void* const* d_in, const int* in_sizes, int n_in,
                              void* d_out, int out_size) {
    const float* x = (const float*)d_in[0];
    float* out = (float*)d_out;
    (void)in_sizes; (void)n_in; (void)out_size;

    cudaFuncSetAttribute(gemm_mma, cudaFuncAttributeMaxDynamicSharedMemorySize,
                         SMEM_TOTAL);

    norm_kernel<<<BATCH, 256>>>(x);
    setup_kernel<<<(BATCH * MSZ) / 256, 256>>>(x);

    dim3 grid(3, BATCH);
    #define GEMM(ia, ib, iy, idst, mode) \
        gemm_mma<<<grid, 512, SMEM_TOTAL>>>(ia, ib, iy, idst, mode, out)

    GEMM(0, 3, 0, 1, 0);   // Y1(1) = A(0)@Z0(3)
    // iter 1
    GEMM(3, 1, 1, 2, 1);   // ZY(2) = 0.5*Y(1) - 0.5*Z(3)@Y(1)
    GEMM(1, 2, 0, 0, 0);   // Y2(0) = Y(1)@ZY(2)
    GEMM(2, 3, 0, 4, 0);   // Z2(4) = ZY(2)@Z(3)
    // iter 2
    GEMM(4, 0, 0, 2, 1);   // ZY(2) = 0.5*Y(0) - 0.5*Z(4)@Y(0)
    GEMM(0, 2, 0, 1, 0);   // Y3(1) = Y(0)@ZY(2)
    GEMM(2, 4, 0, 3, 0);   // Z3(3) = ZY(2)@Z(4)
    // iter 3
    GEMM(3, 1, 1, 2, 1);   // ZY(2) = 0.5*Y(1) - 0.5*Z(3)@Y(1)
    GEMM(1, 2, 0, 0, 0);   // Y4(0) = Y(1)@ZY(2)
    GEMM(2, 3, 0, 4, 0);   // Z4(4) = ZY(2)@Z(3)
    // final
    GEMM(0, 4, 0, 2, 1);   // T(2) = 0.5*Y(0) - 0.5*Y(0)@Z(4)
    GEMM(2, 0, 0, 0, 2);   // out = T(2)@Y(0) * sqrt(normA)
    #undef GEMM
}

// round 7
// speedup vs baseline: 1.5143x; 1.2478x over previous
#include <cuda_runtime.h>
#include <cuda_bf16.h>
#include <cstdint>
#include <math.h>

// Sqrtm Newton-Schulz on tensor cores via mma.sync bf16 (sm_80+ PTX; harness
// PTX target is plain sm_103, which rejects tcgen05).
// Chain (verified):
//   normA = sum(x); A = x/normA; Z0 = 1.5I - 0.5A
//   Y1 = A@Z0
//   3x: ZY = 0.5*Y - 0.5*(Z@Y); Y' = Y@ZY; Z' = ZY@Z
//   T = 0.5*Y - 0.5*(Y@Z); out = (T@Y)*sqrt(normA)
// All chain matrices are symmetric => outputs symmetric => compute 6 of 8
// 128x64 tiles; tiles (0,2),(0,3) also emit the transposed lower-left half.
// fp32 stored as bf16 hi+lo; product via 3 MMAs: Ah@Bh + Ah@Bl + Al@Bh.
//
// R7: CTA tile 128x64, 256 thr, 8 warps (4M x 2N, 32x32 each), 96KB smem
// => 2 resident CTAs/SM with independent sync phases (LDSM/MMA overlap).

#define DMAT 256
#define MSZ  65536
#define BATCH 256

#define STAGE 49152              // Ah 16K | Al 16K | Bh 8K | Bl 8K
#define OFF_BH 32768
#define OFF_BL 40960
#define SMEM_TOTAL (2 * STAGE)   // 96 KB

__device__ __nv_bfloat16 g_hi[5][(size_t)BATCH * MSZ];
__device__ __nv_bfloat16 g_lo[5][(size_t)BATCH * MSZ];
__device__ float g_inv[BATCH];
__device__ float g_sqrt[BATCH];

__device__ __forceinline__ uint32_t smem_u32(const void* p) {
    uint32_t a;
    asm("{ .reg .u64 t; cvta.to.shared.u64 t, %1; cvt.u32.u64 %0, t; }" : "=r"(a) : "l"(p));
    return a;
}

#define LDSM4(r, a) \
    asm volatile("ldmatrix.sync.aligned.m8n8.x4.shared.b16 {%0,%1,%2,%3}, [%4];" \
        : "=r"((r)[0]), "=r"((r)[1]), "=r"((r)[2]), "=r"((r)[3]) : "r"(a))

#define MMA(d, a, bb) \
    asm volatile("mma.sync.aligned.m16n8k16.row.col.f32.bf16.bf16.f32 " \
        "{%0,%1,%2,%3}, {%4,%5,%6,%7}, {%8,%9}, {%0,%1,%2,%3};" \
        : "+f"((d)[0]), "+f"((d)[1]), "+f"((d)[2]), "+f"((d)[3]) \
        : "r"((a)[0]), "r"((a)[1]), "r"((a)[2]), "r"((a)[3]), \
          "r"((bb)[0]), "r"((bb)[1]))

// ---------------------------------------------------------------------------
__global__ void norm_kernel(const float* __restrict__ x) {
    const int b = blockIdx.x;
    const float* p = x + (size_t)b * MSZ;
    float s = 0.f;
    for (int i = threadIdx.x; i < MSZ; i += 256) s += p[i];
    __shared__ float sh[256];
    sh[threadIdx.x] = s;
    __syncthreads();
    for (int off = 128; off > 0; off >>= 1) {
        if (threadIdx.x < off) sh[threadIdx.x] += sh[threadIdx.x + off];
        __syncthreads();
    }
    if (threadIdx.x == 0) {
        float n = sh[0];
        g_inv[b] = 1.0f / n;
        g_sqrt[b] = sqrtf(n);
    }
}

// A = x*inv -> buf0;  Z0 = 1.5I - 0.5A -> buf3  (bf16 hi/lo pairs)
__global__ void setup_kernel(const float* __restrict__ x) {
    const size_t idx = (size_t)blockIdx.x * blockDim.x + threadIdx.x;
    const int b = (int)(idx >> 16);
    const int ij = (int)(idx & (MSZ - 1));
    const float a = x[idx] * g_inv[b];
    const int i = ij >> 8, j = ij & 255;
    const float z = (i == j ? 1.5f : 0.0f) - 0.5f * a;

    __nv_bfloat16 ah = __float2bfloat16_rn(a);
    __nv_bfloat16 al = __float2bfloat16_rn(a - __bfloat162float(ah));
    __nv_bfloat16 zh = __float2bfloat16_rn(z);
    __nv_bfloat16 zl = __float2bfloat16_rn(z - __bfloat162float(zh));
    g_hi[0][idx] = ah;  g_lo[0][idx] = al;
    g_hi[3][idx] = zh;  g_lo[3][idx] = zl;
}

// ---------------------------------------------------------------------------
// Batched GEMM step. grid = (6 tiles, BATCH). 256 threads, 8 warps (4M x 2N),
// warp tile 32x32, CTA tile 128x64.
// Tile map: 0..3 -> (rows 0..127, cols 64*t); 4,5 -> (rows 128..255,
// cols 128 / 192). Tiles 2,3 also write transposed mirror to rows 128+64*(t-2).
// mode 0: C = A@B               -> hi/lo pair in buf idst
// mode 1: C = 0.5*Y - 0.5*(A@B) -> pair in buf idst   (Y = buf iy)
// mode 2: C = (A@B)*sqrt(normA) -> fp32 to outp
__global__ void __launch_bounds__(256, 2)
gemm_mma(int ia, int ib, int iy, int idst, int mode, float* __restrict__ outp)
{
    extern __shared__ __align__(128) char smem[];
    const uint32_t sbase = smem_u32(smem);
    const int tid = threadIdx.x, wid = tid >> 5, lane = tid & 31;
    const int tileId = blockIdx.x;
    const int b = blockIdx.y;
    const int mBase = (tileId >= 4) ? 128 : 0;
    const int nBase = (tileId < 4) ? tileId * 64 : (tileId - 2) * 64;
    const bool mir = (tileId == 2) || (tileId == 3);
    const size_t mo = (size_t)b * MSZ;

    const __nv_bfloat16* Ah = g_hi[ia] + mo;
    const __nv_bfloat16* Al = g_lo[ia] + mo;
    const __nv_bfloat16* Bh = g_hi[ib] + mo;
    const __nv_bfloat16* Bl = g_lo[ib] + mo;

    const int warpM = wid & 3;   // 4 warps over M (32 rows each)
    const int warpN = wid >> 2;  // 2 warps over N (32 cols each)

    float acc[2][4][4] = {};     // [mt][nt][frag]

    // ---- global -> smem (cp.async), one K-chunk of 64 cols, 4 planes ----
    auto load_chunk = [&](int stage, int c) {
        const uint32_t sb = sbase + stage * STAGE;
        const int kc = c * 64;
        #pragma unroll
        for (int it = 0; it < 12; ++it) {
            const int i = tid + it * 256;        // 0..3071
            int plane, row, gRow;
            uint32_t dstOff;
            if (i < 2048) {                      // A: 2 planes x 128 rows x 8
                plane = i >> 10;
                const int rem = i & 1023;
                row = rem >> 3;
                gRow = mBase + row;
                dstOff = plane * 16384u;
            } else {                             // B: 2 planes x 64 rows x 8
                const int j = i - 2048;
                plane = j >> 9;
                const int rem = j & 511;
                row = rem >> 3;
                gRow = nBase + row;
                dstOff = OFF_BH + plane * 8192u;
            }
            const int seg = i & 7;
            const __nv_bfloat16* sp =
                (i < 2048) ? (plane ? Al : Ah) : (plane ? Bl : Bh);
            const void* src = sp + (size_t)gRow * DMAT + kc + seg * 8;
            const uint32_t dst = sb + dstOff + row * 128 +
                                 ((seg ^ (row & 7)) * 16);
            asm volatile("cp.async.cg.shared.global [%0], [%1], 16;"
                         :: "r"(dst), "l"(src));
        }
        asm volatile("cp.async.commit_group;" ::: "memory");
    };

    // ---- compute one K-chunk (4 x k16 steps), 3-product split ----
    const int r16 = lane & 15, chf = lane >> 4, xr = lane & 7;
    const uint32_t aRow0 = (uint32_t)(warpM * 32 + r16) * 128;
    const uint32_t bRow0 = OFF_BH + (uint32_t)(warpN * 32 + r16) * 128;

    auto compute_chunk = [&](int stage) {
        const uint32_t sb = sbase + stage * STAGE;
        #pragma unroll
        for (int ks = 0; ks < 4; ++ks) {
            const uint32_t sw = (uint32_t)(((ks * 2 + chf) ^ xr) * 16);
            uint32_t ahf[2][4], alf[2][4], bhf[4][2], blf[4][2];
            #pragma unroll
            for (int mt = 0; mt < 2; ++mt) {
                const uint32_t addr = sb + aRow0 + (uint32_t)(mt * 2048) + sw;
                LDSM4(ahf[mt], addr);            // plane Ah
                LDSM4(alf[mt], addr + 16384);    // plane Al
            }
            #pragma unroll
            for (int np = 0; np < 2; ++np) {
                const uint32_t addr = sb + bRow0 + (uint32_t)(np * 2048) + sw;
                uint32_t t[4];
                LDSM4(t, addr);                  // plane Bh
                bhf[np * 2][0] = t[0];      bhf[np * 2][1] = t[2];
                bhf[np * 2 + 1][0] = t[1];  bhf[np * 2 + 1][1] = t[3];
                LDSM4(t, addr + 8192);           // plane Bl
                blf[np * 2][0] = t[0];      blf[np * 2][1] = t[2];
                blf[np * 2 + 1][0] = t[1];  blf[np * 2 + 1][1] = t[3];
            }
            #pragma unroll
            for (int mt = 0; mt < 2; ++mt)
                #pragma unroll
                for (int nt = 0; nt < 4; ++nt)
                    MMA(acc[mt][nt], ahf[mt], bhf[nt]);
            #pragma unroll
            for (int mt = 0; mt < 2; ++mt)
                #pragma unroll
                for (int nt = 0; nt < 4; ++nt)
                    MMA(acc[mt][nt], ahf[mt], blf[nt]);
            #pragma unroll
            for (int mt = 0; mt < 2; ++mt)
                #pragma unroll
                for (int nt = 0; nt < 4; ++nt)
                    MMA(acc[mt][nt], alf[mt], bhf[nt]);
        }
    };

    load_chunk(0, 0);
    load_chunk(1, 1);
    #pragma unroll
    for (int c = 0; c < 4; ++c) {
        if (c < 3) asm volatile("cp.async.wait_group 1;" ::: "memory");
        else       asm volatile("cp.async.wait_group 0;" ::: "memory");
        __syncthreads();
        compute_chunk(c & 1);
        __syncthreads();
        if (c < 2) load_chunk(c & 1, c + 2);
    }

    // ---- epilogue ----
    const float sc = g_sqrt[b];
    const int r4 = lane >> 2, c2 = (lane & 3) * 2;
    const __nv_bfloat16* Yh = g_hi[iy] + mo;
    const __nv_bfloat16* Yl = g_lo[iy] + mo;
    __nv_bfloat16* Dh = g_hi[idst] + mo;
    __nv_bfloat16* Dl = g_lo[idst] + mo;
    float* Of = outp + mo;
    uint32_t* sm32 = (uint32_t*)smem;   // mirror staging, pitch 65 words

    #pragma unroll
    for (int mt = 0; mt < 2; ++mt)
        #pragma unroll
        for (int nt = 0; nt < 4; ++nt)
            #pragma unroll
            for (int h = 0; h < 2; ++h) {
                const int rloc = warpM * 32 + mt * 16 + r4 + h * 8;
                const int cloc = warpN * 32 + nt * 8 + c2;
                const int row = mBase + rloc, col = nBase + cloc;
                float v0 = acc[mt][nt][h * 2];
                float v1 = acc[mt][nt][h * 2 + 1];
                const size_t off = (size_t)row * DMAT + col;
                if (mode == 1) {
                    const uint32_t hw = *(const uint32_t*)(Yh + off);
                    const uint32_t lw = *(const uint32_t*)(Yl + off);
                    const float y0 = __uint_as_float(hw << 16) +
                                     __uint_as_float(lw << 16);
                    const float y1 = __uint_as_float(hw & 0xffff0000u) +
                                     __uint_as_float(lw & 0xffff0000u);
                    v0 = 0.5f * y0 - 0.5f * v0;
                    v1 = 0.5f * y1 - 0.5f * v1;
                }
                if (mode == 2) {
                    v0 *= sc;  v1 *= sc;
                    *(float2*)(Of + off) = make_float2(v0, v1);
                    if (mir) {
                        sm32[rloc * 65 + cloc]     = __float_as_uint(v0);
                        sm32[rloc * 65 + cloc + 1] = __float_as_uint(v1);
                    }
                } else {
                    const __nv_bfloat16 h0 = __float2bfloat16_rn(v0);
                    const __nv_bfloat16 h1 = __float2bfloat16_rn(v1);
                    const __nv_bfloat16 l0 =
                        __float2bfloat16_rn(v0 - __bfloat162float(h0));
                    const __nv_bfloat16 l1 =
                        __float2bfloat16_rn(v1 - __bfloat162float(h1));
                    __nv_bfloat162 hp = __halves2bfloat162(h0, h1);
                    __nv_bfloat162 lp = __halves2bfloat162(l0, l1);
                    const uint32_t hpw = *(uint32_t*)&hp;
                    const uint32_t lpw = *(uint32_t*)&lp;
                    *(uint32_t*)(Dh + off) = hpw;
                    *(uint32_t*)(Dl + off) = lpw;
                    if (mir) {
                        // pack (hi, lo) of each element into one word
                        sm32[rloc * 65 + cloc] =
                            (hpw & 0xffffu) | (lpw << 16);
                        sm32[rloc * 65 + cloc + 1] =
                            (hpw >> 16) | (lpw & 0xffff0000u);
                    }
                }
            }

    if (mir) {
        __syncthreads();
        // mirror block: rows mrBase..mrBase+63, cols 0..127.
        // element (mrBase+i, j) = tile-local (row j, col i) = sm32[j*65+i]
        const int mrBase = 128 + (tileId - 2) * 64;
        #pragma unroll
        for (int it = 0; it < 16; ++it) {
            const int e = tid + it * 256;         // 0..4095 (pairs)
            const int i = e >> 6;                 // mirror row 0..63
            const int j = (e & 63) * 2;           // mirror col, even
            const uint32_t w0 = sm32[j * 65 + i];
            const uint32_t w1 = sm32[(j + 1) * 65 + i];
            const size_t off = (size_t)(mrBase + i) * DMAT + j;
            if (mode == 2) {
                *(float2*)(Of + off) =
                    make_float2(__uint_as_float(w0), __uint_as_float(w1));
            } else {
                *(uint32_t*)(Dh + off) = (w0 & 0xffffu) | (w1 << 16);
                *(uint32_t*)(Dl + off) = (w0 >> 16) | (w1 & 0xffff0000u);
            }
        }
    }
}

// ---------------------------------------------------------------------------
extern "C" void kernel_launch(void* const* d_in, const int* in_sizes, int n_in,
                              void* d_out, int out_size) {
    const float* x = (const float*)d_in[0];
    float* out = (float*)d_out;
    (void)in_sizes; (void)n_in; (void)out_size;

    cudaFuncSetAttribute(gemm_mma, cudaFuncAttributeMaxDynamicSharedMemorySize,
                         SMEM_TOTAL);

    norm_kernel<<<BATCH, 256>>>(x);
    setup_kernel<<<(BATCH * MSZ) / 256, 256>>>(x);

    dim3 grid(6, BATCH);
    #define GEMM(ia, ib, iy, idst, mode) \
        gemm_mma<<<grid, 256, SMEM_TOTAL>>>(ia, ib, iy, idst, mode, out)

    GEMM(0, 3, 0, 1, 0);   // Y1(1) = A(0)@Z0(3)
    // iter 1
    GEMM(3, 1, 1, 2, 1);   // ZY(2) = 0.5*Y(1) - 0.5*Z(3)@Y(1)
    GEMM(1, 2, 0, 0, 0);   // Y2(0) = Y(1)@ZY(2)
    GEMM(2, 3, 0, 4, 0);   // Z2(4) = ZY(2)@Z(3)
    // iter 2
    GEMM(4, 0, 0, 2, 1);   // ZY(2) = 0.5*Y(0) - 0.5*Z(4)@Y(0)
    GEMM(0, 2, 0, 1, 0);   // Y3(1) = Y(0)@ZY(2)
    GEMM(2, 4, 0, 3, 0);   // Z3(3) = ZY(2)@Z(4)
    // iter 3
    GEMM(3, 1, 1, 2, 1);   // ZY(2) = 0.5*Y(1) - 0.5*Z(3)@Y(1)
    GEMM(1, 2, 0, 0, 0);   // Y4(0) = Y(1)@ZY(2)
    GEMM(2, 3, 0, 4, 0);   // Z4(4) = ZY(2)@Z(3)
    // final
    GEMM(0, 4, 0, 2, 1);   // T(2) = 0.5*Y(0) - 0.5*Y(0)@Z(4)
    GEMM(2, 0, 0, 0, 2);   // out = T(2)@Y(0) * sqrt(normA)
    #undef GEMM
}